// round 9
// baseline (speedup 1.0000x reference)
#include <cuda_runtime.h>

// Segment mean pooling: x [524288,128] f32, pointer [1025] i32 -> out [1024,128] f32.
//
// Kernel 1: zero out.
// Kernel 2: grid 1024 x 512-row chunks. Per CTA-uniform segment intersection,
//   8 warps x 32 float4-columns accumulate with an EXPLICIT 4-deep load batch
//   (4 independent LDG.128 issued back-to-back, tree-summed) and
//   __launch_bounds__(256,4) so ptxas has a 64-reg budget to keep them all in
//   flight (R8 showed the 32-reg default serializes the loads).
//   Flush: smem-reduce 8 warps -> 1, warp 0 scalar-atomicAdds inv-scaled
//   partials into out (sum of scaled partials == mean).

#define D_FEAT 128
#define D4 (D_FEAT / 4)     // 32 float4 per row
#define CHUNK 512           // rows per CTA

__global__ __launch_bounds__(128) void zero_out_kernel(float4* __restrict__ out4, int n4)
{
    int i = blockIdx.x * blockDim.x + threadIdx.x;
    if (i < n4) out4[i] = make_float4(0.f, 0.f, 0.f, 0.f);
}

__global__ __launch_bounds__(256, 4) void seg_accum_kernel(
    const float4* __restrict__ x4,
    const int* __restrict__ ptr,
    float* __restrict__ out,
    int n_rows, int n_segs)
{
    const int base = blockIdx.x * CHUNK;
    if (base >= n_rows) return;
    const int cend = min(base + CHUNK, n_rows);
    const int c4 = threadIdx.x & 31;   // float4 column 0..31
    const int r  = threadIdx.x >> 5;   // row-lane warp 0..7

    __shared__ float4 sred[8][D4];     // 4 KB

    // First segment overlapping the chunk (CTA-uniform -> broadcast L1 hits).
    int lo = 0, hi = n_segs - 1;
    while (lo < hi) {
        int mid = (lo + hi + 1) >> 1;
        if (__ldg(ptr + mid) <= base) lo = mid; else hi = mid - 1;
    }
    int seg = lo;

    for (;;) {
        const int seg_beg = __ldg(ptr + seg);
        const int seg_end = __ldg(ptr + seg + 1);
        const int s = max(seg_beg, base);
        const int e = min(seg_end, cend);

        float4 acc = make_float4(0.f, 0.f, 0.f, 0.f);
        int row = s + r;

        // Batched main loop: 4 independent loads in flight, tree reduction.
        for (; row + 24 < e; row += 32) {
            const float4 v0 = x4[(size_t)(row +  0) * D4 + c4];
            const float4 v1 = x4[(size_t)(row +  8) * D4 + c4];
            const float4 v2 = x4[(size_t)(row + 16) * D4 + c4];
            const float4 v3 = x4[(size_t)(row + 24) * D4 + c4];
            float4 t0, t1;
            t0.x = v0.x + v1.x; t0.y = v0.y + v1.y; t0.z = v0.z + v1.z; t0.w = v0.w + v1.w;
            t1.x = v2.x + v3.x; t1.y = v2.y + v3.y; t1.z = v2.z + v3.z; t1.w = v2.w + v3.w;
            acc.x += t0.x + t1.x; acc.y += t0.y + t1.y;
            acc.z += t0.z + t1.z; acc.w += t0.w + t1.w;
        }
        for (; row < e; row += 8) {
            const float4 v = x4[(size_t)row * D4 + c4];
            acc.x += v.x; acc.y += v.y; acc.z += v.z; acc.w += v.w;
        }

        // 8 warp-partials -> 1; warp 0 flushes the inv-scaled partial.
        sred[r][c4] = acc;
        __syncthreads();
        if (r == 0 && e > s) {
            #pragma unroll
            for (int i = 1; i < 8; i++) {
                const float4 v = sred[i][c4];
                acc.x += v.x; acc.y += v.y; acc.z += v.z; acc.w += v.w;
            }
            const float inv = 1.0f / (float)(seg_end - seg_beg);
            float* o = out + (size_t)seg * D_FEAT + c4 * 4;
            atomicAdd(o + 0, acc.x * inv);
            atomicAdd(o + 1, acc.y * inv);
            atomicAdd(o + 2, acc.z * inv);
            atomicAdd(o + 3, acc.w * inv);
        }
        if (seg_end >= cend) break;
        seg++;
        __syncthreads();   // sred reuse safety
    }
}

extern "C" void kernel_launch(void* const* d_in, const int* in_sizes, int n_in,
                              void* d_out, int out_size)
{
    const float4* x4  = (const float4*)d_in[0];
    const int*    ptr = (const int*)d_in[1];
    float*        out = (float*)d_out;

    const int n_rows = in_sizes[0] / D_FEAT;   // 524288
    const int n_segs = in_sizes[1] - 1;        // 1024
    const int out_f4 = out_size / 4;           // 32768

    zero_out_kernel<<<(out_f4 + 127) / 128, 128>>>((float4*)out, out_f4);

    const int n_chunks = (n_rows + CHUNK - 1) / CHUNK;   // 1024
    seg_accum_kernel<<<n_chunks, 256>>>(x4, ptr, out, n_rows, n_segs);
}

// round 10
// speedup vs baseline: 1.0651x; 1.0651x over previous
#include <cuda_runtime.h>

// Segment mean pooling: x [524288,128] f32, pointer [1025] i32 -> out [1024,128] f32.
//
// Step 1: cudaMemsetAsync(out, 0) — graph-capturable memset node, cheaper than
//         a zero kernel (out is poisoned by the harness).
// Step 2: R4 engine + streaming loads: grid 1024 x 512-row chunks, 8 warps x
//         32 float4-columns, stride-8 rows, unroll 4, __ldcs (evict-first,
//         read-once data; keeps L2 for the pointer/atomic working set).
//         Per CTA-uniform segment intersection: smem-reduce 8 warp partials,
//         warp 0 scalar-atomicAdds inv-scaled partials into out
//         (sum of scaled partials == mean).

#define D_FEAT 128
#define D4 (D_FEAT / 4)     // 32 float4 per row
#define CHUNK 512           // rows per CTA

__global__ __launch_bounds__(256) void seg_accum_kernel(
    const float4* __restrict__ x4,
    const int* __restrict__ ptr,
    float* __restrict__ out,
    int n_rows, int n_segs)
{
    const int base = blockIdx.x * CHUNK;
    if (base >= n_rows) return;
    const int cend = min(base + CHUNK, n_rows);
    const int c4 = threadIdx.x & 31;   // float4 column 0..31
    const int r  = threadIdx.x >> 5;   // row-lane warp 0..7

    __shared__ float4 sred[8][D4];     // 4 KB

    // First segment overlapping the chunk (CTA-uniform -> broadcast L1 hits).
    int lo = 0, hi = n_segs - 1;
    while (lo < hi) {
        int mid = (lo + hi + 1) >> 1;
        if (__ldg(ptr + mid) <= base) lo = mid; else hi = mid - 1;
    }
    int seg = lo;

    for (;;) {
        const int seg_beg = __ldg(ptr + seg);
        const int seg_end = __ldg(ptr + seg + 1);
        const int s = max(seg_beg, base);
        const int e = min(seg_end, cend);

        float4 acc = make_float4(0.f, 0.f, 0.f, 0.f);
        #pragma unroll 4
        for (int row = s + r; row < e; row += 8) {
            const float4 v = __ldcs(x4 + (size_t)row * D4 + c4);  // streaming
            acc.x += v.x; acc.y += v.y; acc.z += v.z; acc.w += v.w;
        }

        // 8 warp-partials -> 1; warp 0 flushes the inv-scaled partial.
        sred[r][c4] = acc;
        __syncthreads();
        if (r == 0 && e > s) {
            #pragma unroll
            for (int i = 1; i < 8; i++) {
                const float4 v = sred[i][c4];
                acc.x += v.x; acc.y += v.y; acc.z += v.z; acc.w += v.w;
            }
            const float inv = 1.0f / (float)(seg_end - seg_beg);
            float* o = out + (size_t)seg * D_FEAT + c4 * 4;
            atomicAdd(o + 0, acc.x * inv);
            atomicAdd(o + 1, acc.y * inv);
            atomicAdd(o + 2, acc.z * inv);
            atomicAdd(o + 3, acc.w * inv);
        }
        if (seg_end >= cend) break;
        seg++;
        __syncthreads();   // sred reuse safety
    }
}

extern "C" void kernel_launch(void* const* d_in, const int* in_sizes, int n_in,
                              void* d_out, int out_size)
{
    const float4* x4  = (const float4*)d_in[0];
    const int*    ptr = (const int*)d_in[1];
    float*        out = (float*)d_out;

    const int n_rows = in_sizes[0] / D_FEAT;   // 524288
    const int n_segs = in_sizes[1] - 1;        // 1024

    // Zero the output via a memset node (async, graph-capturable).
    cudaMemsetAsync(out, 0, (size_t)out_size * sizeof(float), 0);

    const int n_chunks = (n_rows + CHUNK - 1) / CHUNK;   // 1024
    seg_accum_kernel<<<n_chunks, 256>>>(x4, ptr, out, n_rows, n_segs);
}